// round 3
// baseline (speedup 1.0000x reference)
#include <cuda_runtime.h>
#include <math.h>

// CRF log-likelihood: N=2048, T=200, L=129.
//   numerator: gold-path score (trivial)
//   denominator: forward algorithm, restructured so the inner L x L logsumexp
//   becomes an fp32 matvec against E_ij = exp(T_ij - colmax_j), with only L
//   exp + L log per (seq, step).

#define N_SEQ 2048
#define T_LEN 200
#define L_TAG 129
#define LP    132           // padded column stride (16B-aligned)
#define B_SEQ 8             // sequences per block
#define NBLK  (N_SEQ / B_SEQ)   // 256
#define MTHREADS 160

__device__ float g_E[L_TAG * LP];   // exp(T_ij - m_j), row i stride LP
__device__ float g_m[LP];           // per-column max of transitions
__device__ int   g_order[N_SEQ];    // sequences sorted by length
__device__ float g_partial[NBLK];

// ---------------------------------------------------------------------------
// Prep: column maxes, E matrix, deterministic length-sort (counting ranks).
// ---------------------------------------------------------------------------
__global__ void prep_kernel(const float* __restrict__ trans,
                            const int*   __restrict__ lengths) {
    __shared__ int   s_len[N_SEQ];
    __shared__ float s_m[L_TAG];
    int tid = threadIdx.x;

    for (int n = tid; n < N_SEQ; n += 256) s_len[n] = lengths[n];
    if (tid < L_TAG) {
        float mx = -INFINITY;
        for (int i = 0; i < L_TAG; i++) mx = fmaxf(mx, trans[i * L_TAG + tid]);
        s_m[tid] = mx;
        g_m[tid] = mx;
    }
    __syncthreads();

    for (int idx = tid; idx < L_TAG * LP; idx += 256) {
        int i = idx / LP, j = idx % LP;
        g_E[idx] = (j < L_TAG) ? __expf(trans[i * L_TAG + j] - s_m[j]) : 0.0f;
    }

    // Deterministic rank sort by length (ties broken by index).
    for (int n = tid; n < N_SEQ; n += 256) {
        int ln = s_len[n];
        int rank = 0;
        for (int m2 = 0; m2 < N_SEQ; m2++) {
            int lm = s_len[m2];
            rank += (lm < ln) || (lm == ln && m2 < n);
        }
        g_order[rank] = n;
    }
}

// ---------------------------------------------------------------------------
// Main: one block = 8 length-similar sequences; thread j owns tag-column j.
// ---------------------------------------------------------------------------
__global__ void __launch_bounds__(MTHREADS, 2)
crf_main(const float* __restrict__ score,
         const float* __restrict__ trans,
         const float* __restrict__ startt,
         const float* __restrict__ endt,
         const int*   __restrict__ gold,
         const int*   __restrict__ lengths) {
    extern __shared__ float sm[];
    float* E_s     = sm;                       // L_TAG*LP
    float* p_s     = E_s + L_TAG * LP;         // LP*8   (layout [i][b])
    float* red     = p_s + LP * 8;             // 8*LP
    float* amax_s  = red + 8 * LP;             // 8
    float* denom_s = amax_s + 8;               // 8
    float* numer_s = denom_s + 8;              // 8

    int tid = threadIdx.x;

    // Stage E into shared (float4).
    {
        const float4* Eg  = (const float4*)g_E;
        float4*       Es4 = (float4*)E_s;
        for (int idx = tid; idx < (L_TAG * LP) / 4; idx += MTHREADS)
            Es4[idx] = Eg[idx];
    }
    // -inf pads so the max-reduction over [0,LP) is correct.
    if (tid < 8 * (LP - L_TAG)) {
        int b = tid / (LP - L_TAG), jp = L_TAG + tid % (LP - L_TAG);
        red[b * LP + jp] = -INFINITY;
    }

    int seq[B_SEQ], len[B_SEQ];
    int maxlen = 1;
#pragma unroll
    for (int b = 0; b < B_SEQ; b++) {
        seq[b] = g_order[blockIdx.x * B_SEQ + b];
        len[b] = lengths[seq[b]];
        maxlen = max(maxlen, len[b]);
    }

    bool act = (tid < L_TAG);
    int  j   = act ? tid : 0;
    float m_j  = g_m[j];
    float st_j = startt[j];

    float alpha[B_SEQ];
#pragma unroll
    for (int b = 0; b < B_SEQ; b++)
        alpha[b] = st_j + score[(seq[b] * T_LEN + 0) * L_TAG + j];

    if (act) {
#pragma unroll
        for (int b = 0; b < B_SEQ; b++) red[b * LP + j] = alpha[b];
    }
    __syncthreads();

    float amax[B_SEQ];
    {
        int g = tid >> 4, l16 = tid & 15;
        if (g < 8) {
            float mx = -INFINITY;
            for (int jj = l16; jj < LP; jj += 16) mx = fmaxf(mx, red[g * LP + jj]);
#pragma unroll
            for (int o = 8; o; o >>= 1) mx = fmaxf(mx, __shfl_xor_sync(0xffffffffu, mx, o));
            if (l16 == 0) amax_s[g] = mx;
        }
    }
    __syncthreads();
#pragma unroll
    for (int b = 0; b < B_SEQ; b++) amax[b] = amax_s[b];

    for (int t = 1; t < maxlen; t++) {
        // p[i][b] = exp(alpha_b[i] - amax_b), written by thread i.
        if (act) {
            float4 pa, pb;
            pa.x = __expf(alpha[0] - amax[0]); pa.y = __expf(alpha[1] - amax[1]);
            pa.z = __expf(alpha[2] - amax[2]); pa.w = __expf(alpha[3] - amax[3]);
            pb.x = __expf(alpha[4] - amax[4]); pb.y = __expf(alpha[5] - amax[5]);
            pb.z = __expf(alpha[6] - amax[6]); pb.w = __expf(alpha[7] - amax[7]);
            *(float4*)&p_s[j * 8]     = pa;
            *(float4*)&p_s[j * 8 + 4] = pb;
        }
        __syncthreads();

        // Prefetch emissions for this step (coalesced over j).
        float sc[B_SEQ];
        if (act) {
#pragma unroll
            for (int b = 0; b < B_SEQ; b++)
                sc[b] = score[(seq[b] * T_LEN + t) * L_TAG + j];
        }

        // Matvec: acc_b = sum_i p[i][b] * E[i][j]
        float acc[B_SEQ];
#pragma unroll
        for (int b = 0; b < B_SEQ; b++) acc[b] = 0.0f;
        if (act) {
            const float* Ecol = E_s + j;
#pragma unroll 3
            for (int i = 0; i < L_TAG; i++) {
                float  e  = Ecol[i * LP];
                float4 pA = *(const float4*)(p_s + i * 8);
                float4 pB = *(const float4*)(p_s + i * 8 + 4);
                acc[0] = fmaf(e, pA.x, acc[0]);
                acc[1] = fmaf(e, pA.y, acc[1]);
                acc[2] = fmaf(e, pA.z, acc[2]);
                acc[3] = fmaf(e, pA.w, acc[3]);
                acc[4] = fmaf(e, pB.x, acc[4]);
                acc[5] = fmaf(e, pB.y, acc[5]);
                acc[6] = fmaf(e, pB.z, acc[6]);
                acc[7] = fmaf(e, pB.w, acc[7]);
            }
        }

        // alpha update (masked per sequence) + stage for amax reduction.
        if (act) {
#pragma unroll
            for (int b = 0; b < B_SEQ; b++) {
                float na = __logf(acc[b]) + amax[b] + m_j + sc[b];
                if (t < len[b]) alpha[b] = na;
                red[b * LP + j] = alpha[b];
            }
        }
        __syncthreads();

        {
            int g = tid >> 4, l16 = tid & 15;
            if (g < 8) {
                float mx = -INFINITY;
                for (int jj = l16; jj < LP; jj += 16) mx = fmaxf(mx, red[g * LP + jj]);
#pragma unroll
                for (int o = 8; o; o >>= 1) mx = fmaxf(mx, __shfl_xor_sync(0xffffffffu, mx, o));
                if (l16 == 0) amax_s[g] = mx;
            }
        }
        __syncthreads();
#pragma unroll
        for (int b = 0; b < B_SEQ; b++) amax[b] = amax_s[b];
    }

    // Denominator: logsumexp(alpha + end).
    if (act) {
        float e_j = endt[j];
#pragma unroll
        for (int b = 0; b < B_SEQ; b++) red[b * LP + j] = alpha[b] + e_j;
    }
    __syncthreads();
    {
        int g = tid >> 4, l16 = tid & 15;
        if (g < 8) {
            float mx = -INFINITY;
            for (int jj = l16; jj < LP; jj += 16) mx = fmaxf(mx, red[g * LP + jj]);
#pragma unroll
            for (int o = 8; o; o >>= 1) mx = fmaxf(mx, __shfl_xor_sync(0xffffffffu, mx, o));
            if (l16 == 0) amax_s[g] = mx;
        }
    }
    __syncthreads();
    {
        int g = tid >> 4, l16 = tid & 15;
        if (g < 8) {
            float am = amax_s[g];
            float ssum = 0.0f;
            for (int jj = l16; jj < L_TAG; jj += 16) ssum += __expf(red[g * LP + jj] - am);
#pragma unroll
            for (int o = 8; o; o >>= 1) ssum += __shfl_xor_sync(0xffffffffu, ssum, o);
            if (l16 == 0) denom_s[g] = __logf(ssum) + am;
        }
        // Numerator: gold-path score, one 16-lane group per sequence.
        if (g < 8) {
            int sq = g_order[blockIdx.x * B_SEQ + g];
            int ln = lengths[sq];
            float nacc = 0.0f;
            for (int t = l16; t < ln; t += 16) {
                int gt = gold[sq * T_LEN + t];
                nacc += score[(sq * T_LEN + t) * L_TAG + gt];
                if (t >= 1) {
                    int gp = gold[sq * T_LEN + t - 1];
                    nacc += trans[gp * L_TAG + gt];
                }
            }
#pragma unroll
            for (int o = 8; o; o >>= 1) nacc += __shfl_xor_sync(0xffffffffu, nacc, o);
            if (l16 == 0) {
                int g0 = gold[sq * T_LEN];
                int gl = gold[sq * T_LEN + ln - 1];
                numer_s[g] = nacc + startt[g0] + endt[gl];
            }
        }
    }
    __syncthreads();
    if (tid == 0) {
        float part = 0.0f;
#pragma unroll
        for (int b = 0; b < B_SEQ; b++) part += numer_s[b] - denom_s[b];
        g_partial[blockIdx.x] = part;
    }
}

// ---------------------------------------------------------------------------
// Deterministic final reduction of 256 block partials.
// ---------------------------------------------------------------------------
__global__ void final_kernel(float* __restrict__ out) {
    __shared__ float s[NBLK];
    int tid = threadIdx.x;
    s[tid] = (tid < NBLK) ? g_partial[tid] : 0.0f;
    __syncthreads();
    for (int o = NBLK / 2; o; o >>= 1) {
        if (tid < o) s[tid] += s[tid + o];
        __syncthreads();
    }
    if (tid == 0) out[0] = s[0];
}

extern "C" void kernel_launch(void* const* d_in, const int* in_sizes, int n_in,
                              void* d_out, int out_size) {
    (void)in_sizes; (void)n_in; (void)out_size;
    const float* score   = (const float*)d_in[0];
    const float* trans   = (const float*)d_in[1];
    const float* startt  = (const float*)d_in[2];
    const float* endt    = (const float*)d_in[3];
    const int*   gold    = (const int*)d_in[4];
    const int*   lengths = (const int*)d_in[5];
    float*       out     = (float*)d_out;

    // Non-stream, non-allocating API: legal under graph capture; idempotent.
    size_t smem = (size_t)(L_TAG * LP + LP * 8 + 8 * LP + 8 + 8 + 8) * sizeof(float);
    cudaFuncSetAttribute(crf_main, cudaFuncAttributeMaxDynamicSharedMemorySize, (int)smem);

    prep_kernel<<<1, 256>>>(trans, lengths);
    crf_main<<<NBLK, MTHREADS, smem>>>(score, trans, startt, endt, gold, lengths);
    final_kernel<<<1, 256>>>(out);
}

// round 5
// speedup vs baseline: 1.8642x; 1.8642x over previous
#include <cuda_runtime.h>
#include <math.h>

// CRF log-likelihood: N=2048, T=200, L=129.
// Denominator forward pass restructured: inner LxL logsumexp -> fp32 matvec
// against E_ij = exp(T_ij - colmax_j), packed fma.rn.f32x2, stale-shift
// stabilization (exact), 2 barriers/step, warp-4 handles column 128
// lane-parallel, length-sorted + pairing-balanced CTA assignment.

#define N_SEQ 2048
#define T_LEN 200
#define L_TAG 129
#define LP    132           // E row stride (floats)
#define PSTR  12            // p row stride (floats): conflict-free STS.128
#define B_SEQ 8
#define NBLK  (N_SEQ / B_SEQ)   // 256
#define MTHREADS 160

__device__ float g_E[L_TAG * LP];
__device__ float g_m[LP];
__device__ int   g_order[N_SEQ];
__device__ float g_partial[NBLK];

__device__ __forceinline__ unsigned long long pack_dup(float e) {
    unsigned long long r;
    asm("mov.b64 %0, {%1, %1};" : "=l"(r) : "f"(e));
    return r;
}
__device__ __forceinline__ void fma2(unsigned long long& d,
                                     unsigned long long a,
                                     unsigned long long b) {
    asm("fma.rn.f32x2 %0, %1, %2, %3;" : "=l"(d) : "l"(a), "l"(b), "l"(d));
}
__device__ __forceinline__ void unpack2(unsigned long long v, float& lo, float& hi) {
    asm("mov.b64 {%0, %1}, %2;" : "=f"(lo), "=f"(hi) : "l"(v));
}

// ---------------------------------------------------------------------------
// Prep A: column maxes + E matrix (tiny).
// ---------------------------------------------------------------------------
__global__ void prep_E(const float* __restrict__ trans) {
    __shared__ float s_m[L_TAG];
    int tid = threadIdx.x;
    if (tid < L_TAG) {
        float mx = -INFINITY;
        for (int i = 0; i < L_TAG; i++) mx = fmaxf(mx, trans[i * L_TAG + tid]);
        s_m[tid] = mx;
        g_m[tid] = mx;
    }
    __syncthreads();
    for (int idx = tid; idx < L_TAG * LP; idx += 256) {
        int i = idx / LP, j = idx % LP;
        g_E[idx] = (j < L_TAG) ? __expf(trans[i * L_TAG + j] - s_m[j]) : 0.0f;
    }
}

// ---------------------------------------------------------------------------
// Prep B: deterministic rank sort by length, 1 thread per sequence.
// ---------------------------------------------------------------------------
__global__ void sort_kernel(const int* __restrict__ lengths) {
    __shared__ int s_len[N_SEQ];
    int tid = threadIdx.x;
    for (int i = tid; i < N_SEQ; i += blockDim.x) s_len[i] = lengths[i];
    __syncthreads();
    int n = blockIdx.x * blockDim.x + tid;
    int ln = s_len[n];
    int rank = 0;
    for (int m2 = 0; m2 < N_SEQ; m2++) {
        int lm = s_len[m2];
        rank += (lm < ln) || (lm == ln && m2 < n);
    }
    g_order[rank] = n;
}

// ---------------------------------------------------------------------------
// Main kernel.
// ---------------------------------------------------------------------------
__global__ void __launch_bounds__(MTHREADS, 2)
crf_main(const float* __restrict__ score,
         const float* __restrict__ trans,
         const float* __restrict__ startt,
         const float* __restrict__ endt,
         const int*   __restrict__ gold,
         const int*   __restrict__ lengths) {
    extern __shared__ float sm[];
    float* E_s    = sm;                         // L_TAG*LP
    float* p_s    = E_s + L_TAG * LP;           // LP*PSTR
    float* red0   = p_s + LP * PSTR;            // 8*LP
    float* red1   = red0 + 8 * LP;              // 8*LP
    float* amax_s = red1 + 8 * LP;              // 8
    float* denom_s = amax_s + 8;                // 8
    float* numer_s = denom_s + 8;               // 8

    int tid = threadIdx.x;

    // Stage E into shared.
    {
        const float4* Eg = (const float4*)g_E;
        float4* Es4 = (float4*)E_s;
        for (int idx = tid; idx < (L_TAG * LP) / 4; idx += MTHREADS)
            Es4[idx] = Eg[idx];
    }
    // -inf pads in both red buffers (lanes 129..131 of each row).
    if (tid < 48) {
        float* buf = (tid < 24) ? red0 : red1;
        int r = tid % 24, b = r / 3, jp = L_TAG + r % 3;
        buf[b * LP + jp] = -INFINITY;
    }

    // Pairing-balanced group assignment: bids (s, s+148) land on the same SM;
    // give them length-ranks summing to ~255.
    int bid = blockIdx.x;
    int grp = (bid < 148) ? bid : (403 - bid);

    int seq[B_SEQ], len[B_SEQ];
    int maxlen = 1;
#pragma unroll
    for (int b = 0; b < B_SEQ; b++) {
        seq[b] = g_order[grp * B_SEQ + b];
        len[b] = lengths[seq[b]];
        maxlen = max(maxlen, len[b]);
    }

    bool own = (tid <= 128);           // column owners j = tid (129 of them)
    int  j   = own ? tid : 0;
    float m_j  = g_m[j];
    float st_j = startt[j];

    float alpha[B_SEQ];
#pragma unroll
    for (int b = 0; b < B_SEQ; b++)
        alpha[b] = st_j + score[(seq[b] * T_LEN + 0) * L_TAG + j];

    if (own) {
#pragma unroll
        for (int b = 0; b < B_SEQ; b++) red0[b * LP + j] = alpha[b];
    }
    __syncthreads();

    // Exact amax(alpha_0) -> shift for t=1.
    if (tid < 128) {
        int g = tid >> 4, l16 = tid & 15;
        float mx = -INFINITY;
        for (int jj = l16; jj < LP; jj += 16) mx = fmaxf(mx, red0[g * LP + jj]);
#pragma unroll
        for (int o = 8; o; o >>= 1) mx = fmaxf(mx, __shfl_xor_sync(0xffffffffu, mx, o));
        if (l16 == 0) amax_s[g] = mx;
    }
    __syncthreads();
    float shift[B_SEQ];
#pragma unroll
    for (int b = 0; b < B_SEQ; b++) shift[b] = amax_s[b];

    for (int t = 1; t < maxlen; t++) {
        float* redR = (t & 1) ? red0 : red1;   // alpha_{t-1}
        float* redW = (t & 1) ? red1 : red0;   // alpha_t

        // (A) p = exp(alpha - shift), written by column owners.
        if (own) {
            float4 pa, pb;
            pa.x = __expf(alpha[0] - shift[0]); pa.y = __expf(alpha[1] - shift[1]);
            pa.z = __expf(alpha[2] - shift[2]); pa.w = __expf(alpha[3] - shift[3]);
            pb.x = __expf(alpha[4] - shift[4]); pb.y = __expf(alpha[5] - shift[5]);
            pb.z = __expf(alpha[6] - shift[6]); pb.w = __expf(alpha[7] - shift[7]);
            *(float4*)&p_s[j * PSTR]     = pa;
            *(float4*)&p_s[j * PSTR + 4] = pb;
        }
        __syncthreads();   // sync1: p ready; redR (alpha_{t-1}) ready

        if (tid < 128) {
            // Prefetch emissions (hide LDG under reduction + matvec).
            float sc[B_SEQ];
#pragma unroll
            for (int b = 0; b < B_SEQ; b++)
                sc[b] = score[(seq[b] * T_LEN + t) * L_TAG + j];

            // (C) reduce alpha_{t-1} -> amax_s (shift for t+1), overlapped.
            {
                int g = tid >> 4, l16 = tid & 15;
                float mx = -INFINITY;
                for (int jj = l16; jj < LP; jj += 16) mx = fmaxf(mx, redR[g * LP + jj]);
#pragma unroll
                for (int o = 8; o; o >>= 1) mx = fmaxf(mx, __shfl_xor_sync(0xffffffffu, mx, o));
                if (l16 == 0) amax_s[g] = mx;
            }

            // (D) packed matvec: acc_b = sum_i p[i][b] * E[i][j]
            unsigned long long acc01 = 0ull, acc23 = 0ull, acc45 = 0ull, acc67 = 0ull;
            const float* Ecol = E_s + j;
#pragma unroll 4
            for (int i = 0; i < L_TAG; i++) {
                unsigned long long e2 = pack_dup(Ecol[i * LP]);
                const ulonglong2 P0 = *(const ulonglong2*)(p_s + i * PSTR);
                const ulonglong2 P1 = *(const ulonglong2*)(p_s + i * PSTR + 4);
                fma2(acc01, e2, P0.x);
                fma2(acc23, e2, P0.y);
                fma2(acc45, e2, P1.x);
                fma2(acc67, e2, P1.y);
            }
            float acc[B_SEQ];
            unpack2(acc01, acc[0], acc[1]);
            unpack2(acc23, acc[2], acc[3]);
            unpack2(acc45, acc[4], acc[5]);
            unpack2(acc67, acc[6], acc[7]);

#pragma unroll
            for (int b = 0; b < B_SEQ; b++) {
                float na = __logf(acc[b]) + shift[b] + m_j + sc[b];
                if (t < len[b]) alpha[b] = na;
                redW[b * LP + j] = alpha[b];
            }
        } else {
            // Warp 4: column 128, lane-parallel over i.
            int l = tid - 128;
            float accw[B_SEQ];
#pragma unroll
            for (int b = 0; b < B_SEQ; b++) accw[b] = 0.0f;
            float scw[B_SEQ];
            if (l == 0) {
#pragma unroll
                for (int b = 0; b < B_SEQ; b++)
                    scw[b] = score[(seq[b] * T_LEN + t) * L_TAG + 128];
            }
            for (int i = l; i < L_TAG; i += 32) {
                float e = E_s[i * LP + 128];
                float4 pA = *(const float4*)(p_s + i * PSTR);
                float4 pB = *(const float4*)(p_s + i * PSTR + 4);
                accw[0] = fmaf(e, pA.x, accw[0]);
                accw[1] = fmaf(e, pA.y, accw[1]);
                accw[2] = fmaf(e, pA.z, accw[2]);
                accw[3] = fmaf(e, pA.w, accw[3]);
                accw[4] = fmaf(e, pB.x, accw[4]);
                accw[5] = fmaf(e, pB.y, accw[5]);
                accw[6] = fmaf(e, pB.z, accw[6]);
                accw[7] = fmaf(e, pB.w, accw[7]);
            }
#pragma unroll
            for (int o = 16; o; o >>= 1) {
#pragma unroll
                for (int b = 0; b < B_SEQ; b++)
                    accw[b] += __shfl_xor_sync(0xffffffffu, accw[b], o);
            }
            if (l == 0) {
#pragma unroll
                for (int b = 0; b < B_SEQ; b++) {
                    float na = __logf(accw[b]) + shift[b] + m_j + scw[b];
                    if (t < len[b]) alpha[b] = na;
                    redW[b * LP + 128] = alpha[b];
                }
            }
        }
        __syncthreads();   // sync2: amax_s + redW visible
#pragma unroll
        for (int b = 0; b < B_SEQ; b++) shift[b] = amax_s[b];
    }

    // ---- Epilogue: denominator logsumexp + numerator ----
    if (own) {
        float e_j = endt[j];
#pragma unroll
        for (int b = 0; b < B_SEQ; b++) red0[b * LP + j] = alpha[b] + e_j;
    }
    __syncthreads();
    if (tid < 128) {
        int g = tid >> 4, l16 = tid & 15;
        float mx = -INFINITY;
        for (int jj = l16; jj < LP; jj += 16) mx = fmaxf(mx, red0[g * LP + jj]);
#pragma unroll
        for (int o = 8; o; o >>= 1) mx = fmaxf(mx, __shfl_xor_sync(0xffffffffu, mx, o));
        if (l16 == 0) amax_s[g] = mx;
    }
    __syncthreads();
    if (tid < 128) {
        int g = tid >> 4, l16 = tid & 15;
        float am = amax_s[g];
        float ssum = 0.0f;
        for (int jj = l16; jj < L_TAG; jj += 16) ssum += __expf(red0[g * LP + jj] - am);
#pragma unroll
        for (int o = 8; o; o >>= 1) ssum += __shfl_xor_sync(0xffffffffu, ssum, o);
        if (l16 == 0) denom_s[g] = __logf(ssum) + am;

        // Numerator: gold-path score.
        int sq = g_order[grp * B_SEQ + g];
        int ln = lengths[sq];
        float nacc = 0.0f;
        for (int t = l16; t < ln; t += 16) {
            int gt = gold[sq * T_LEN + t];
            nacc += score[(sq * T_LEN + t) * L_TAG + gt];
            if (t >= 1) {
                int gp = gold[sq * T_LEN + t - 1];
                nacc += trans[gp * L_TAG + gt];
            }
        }
#pragma unroll
        for (int o = 8; o; o >>= 1) nacc += __shfl_xor_sync(0xffffffffu, nacc, o);
        if (l16 == 0) {
            int g0 = gold[sq * T_LEN];
            int gl = gold[sq * T_LEN + ln - 1];
            numer_s[g] = nacc + startt[g0] + endt[gl];
        }
    }
    __syncthreads();
    if (tid == 0) {
        float part = 0.0f;
#pragma unroll
        for (int b = 0; b < B_SEQ; b++) part += numer_s[b] - denom_s[b];
        g_partial[blockIdx.x] = part;
    }
}

// ---------------------------------------------------------------------------
// Deterministic final reduction.
// ---------------------------------------------------------------------------
__global__ void final_kernel(float* __restrict__ out) {
    __shared__ float s[NBLK];
    int tid = threadIdx.x;
    s[tid] = g_partial[tid];
    __syncthreads();
    for (int o = NBLK / 2; o; o >>= 1) {
        if (tid < o) s[tid] += s[tid + o];
        __syncthreads();
    }
    if (tid == 0) out[0] = s[0];
}

extern "C" void kernel_launch(void* const* d_in, const int* in_sizes, int n_in,
                              void* d_out, int out_size) {
    (void)in_sizes; (void)n_in; (void)out_size;
    const float* score   = (const float*)d_in[0];
    const float* trans   = (const float*)d_in[1];
    const float* startt  = (const float*)d_in[2];
    const float* endt    = (const float*)d_in[3];
    const int*   gold    = (const int*)d_in[4];
    const int*   lengths = (const int*)d_in[5];
    float*       out     = (float*)d_out;

    size_t smem = (size_t)(L_TAG * LP + LP * PSTR + 2 * 8 * LP + 24) * sizeof(float);
    cudaFuncSetAttribute(crf_main, cudaFuncAttributeMaxDynamicSharedMemorySize, (int)smem);

    prep_E<<<1, 256>>>(trans);
    sort_kernel<<<N_SEQ / 256, 256>>>(lengths);
    crf_main<<<NBLK, MTHREADS, smem>>>(score, trans, startt, endt, gold, lengths);
    final_kernel<<<1, NBLK>>>(out);
}

// round 7
// speedup vs baseline: 2.1161x; 1.1351x over previous
#include <cuda_runtime.h>
#include <math.h>

// CRF log-likelihood: N=2048, T=200, L=129.
// Forward pass in LINEAR domain: w_j ~ exp(alpha_j) with stale per-warp-anchor
// normalization (rK from previous step) -> ONE barrier per step, no per-step
// max-reduction, no per-step logs (8 exps/thread only). alpha reconstructed
// exactly in epilogue via per-anchor accumulated log-scale C_b.

#define N_SEQ 2048
#define T_LEN 200
#define L_TAG 129
#define LP    132            // E row stride (floats)
#define PSTR  12             // w staging row stride (floats)
#define PBUF  (LP * PSTR)
#define B_SEQ 8
#define NBLK  (N_SEQ / B_SEQ)   // 256
#define MTHREADS 160

__device__ float g_E[L_TAG * LP];
__device__ float g_m[LP];
__device__ int   g_order[N_SEQ];
__device__ float g_partial[NBLK];

__device__ __forceinline__ unsigned long long pack_dup(float e) {
    unsigned long long r;
    asm("mov.b64 %0, {%1, %1};" : "=l"(r) : "f"(e));
    return r;
}
__device__ __forceinline__ void fma2(unsigned long long& d,
                                     unsigned long long a,
                                     unsigned long long b) {
    asm("fma.rn.f32x2 %0, %1, %2, %3;" : "=l"(d) : "l"(a), "l"(b), "l"(d));
}
__device__ __forceinline__ void unpack2(unsigned long long v, float& lo, float& hi) {
    asm("mov.b64 {%0, %1}, %2;" : "=f"(lo), "=f"(hi) : "l"(v));
}

// ---------------------------------------------------------------------------
__global__ void prep_E(const float* __restrict__ trans) {
    __shared__ float s_m[L_TAG];
    int tid = threadIdx.x;
    if (tid < L_TAG) {
        float mx = -INFINITY;
        for (int i = 0; i < L_TAG; i++) mx = fmaxf(mx, trans[i * L_TAG + tid]);
        s_m[tid] = mx;
        g_m[tid] = mx;
    }
    __syncthreads();
    for (int idx = tid; idx < L_TAG * LP; idx += 256) {
        int i = idx / LP, j = idx % LP;
        g_E[idx] = (j < L_TAG) ? __expf(trans[i * L_TAG + j] - s_m[j]) : 0.0f;
    }
}

// ---------------------------------------------------------------------------
__global__ void sort_kernel(const int* __restrict__ lengths) {
    __shared__ int s_len[N_SEQ];
    int tid = threadIdx.x;
    for (int i = tid; i < N_SEQ; i += blockDim.x) s_len[i] = lengths[i];
    __syncthreads();
    int n = blockIdx.x * blockDim.x + tid;
    int ln = s_len[n];
    int rank = 0;
    for (int m2 = 0; m2 < N_SEQ; m2++) {
        int lm = s_len[m2];
        rank += (lm < ln) || (lm == ln && m2 < n);
    }
    g_order[rank] = n;
}

// ---------------------------------------------------------------------------
__global__ void __launch_bounds__(MTHREADS, 2)
crf_main(const float* __restrict__ score,
         const float* __restrict__ trans,
         const float* __restrict__ startt,
         const float* __restrict__ endt,
         const int*   __restrict__ gold,
         const int*   __restrict__ lengths) {
    extern __shared__ float sm[];
    float* E_s    = sm;                    // 17028
    float* wbuf   = E_s + L_TAG * LP;      // 2*PBUF (double-buffered w staging)
    float* red0   = wbuf + 2 * PBUF;       // 8*LP
    float* rks    = red0 + 8 * LP;         // 16 (double-buffered 1/w_anchor)
    float* c_s    = rks + 16;              // 8
    float* amax_s = c_s + 8;               // 8
    float* denom_s = amax_s + 8;           // 8
    float* numer_s = denom_s + 8;          // 8

    int tid = threadIdx.x;
    int wid = tid >> 5, lane = tid & 31;

    // Stage E into shared.
    {
        const float4* Eg = (const float4*)g_E;
        float4* Es4 = (float4*)E_s;
        for (int idx = tid; idx < (L_TAG * LP) / 4; idx += MTHREADS)
            Es4[idx] = Eg[idx];
    }
    // -inf pads in red0 (lanes 129..131 per row).
    if (tid < 24) {
        int b = tid / 3, jp = L_TAG + tid % 3;
        red0[b * LP + jp] = -INFINITY;
    }

    // Pair-balanced group assignment: bids (s, s+148) co-resident -> ranks sum ~255.
    int bid = blockIdx.x;
    int grp = (bid < 148) ? bid : (403 - bid);

    int seq[B_SEQ], len[B_SEQ];
    const float* sp[B_SEQ];
    int maxlen = 1;
#pragma unroll
    for (int b = 0; b < B_SEQ; b++) {
        seq[b] = g_order[grp * B_SEQ + b];
        len[b] = lengths[seq[b]];
        maxlen = max(maxlen, len[b]);
    }

    bool own = (tid <= 128);
    int  j   = own ? tid : 0;
    float m_j = g_m[j];
    float st_j = startt[j];
#pragma unroll
    for (int b = 0; b < B_SEQ; b++) sp[b] = score + (size_t)seq[b] * T_LEN * L_TAG + j;

    // Init: w_j = exp(alpha0_j - alpha0_anchor(b)); anchor_j(b) = 32*(b>>1).
    float w[B_SEQ];
    float anch[B_SEQ];
#pragma unroll
    for (int b = 0; b < B_SEQ; b++) {
        int aj = 32 * (b >> 1);
        anch[b] = startt[aj] + score[(size_t)seq[b] * T_LEN * L_TAG + aj];
        float a0 = st_j + sp[b][0];
        w[b] = __expf(a0 - anch[b]);
    }
    if (own) {
        *(float4*)&wbuf[PBUF + j * PSTR]     = make_float4(w[0], w[1], w[2], w[3]);
        *(float4*)&wbuf[PBUF + j * PSTR + 4] = make_float4(w[4], w[5], w[6], w[7]);
    }
    // Anchor bookkeeping: lane 0 of warps 0..3 owns b = 2*wid, 2*wid+1.
    float C0 = 0.f, C1 = 0.f, pend0 = 0.f, pend1 = 0.f;
    if (lane == 0 && wid < 4) {
        int b0 = 2 * wid;
        C0 = anch[b0];
        C1 = anch[b0 + 1];
        rks[8 + b0] = 1.0f;
        rks[8 + b0 + 1] = 1.0f;
    }
    __syncthreads();

    for (int t = 1; t < maxlen; t++) {
        const float* bufR = wbuf + (t & 1) * PBUF;
        float*       bufW = wbuf + ((t + 1) & 1) * PBUF;
        const float* rkR  = rks + (t & 1) * 8;
        float*       rkW  = rks + ((t + 1) & 1) * 8;

        if (tid < 128) {
            // Emission LDGs first (hide DRAM latency under matvec).
            float sc[B_SEQ];
#pragma unroll
            for (int b = 0; b < B_SEQ; b++) sc[b] = sp[b][t * L_TAG];

            float4 rkA = *(const float4*)rkR;
            float4 rkB = *(const float4*)(rkR + 4);

            // Matvec: u_b = sum_i w_i(b) * E[i][j]   (packed f32x2)
            unsigned long long acc01 = 0ull, acc23 = 0ull, acc45 = 0ull, acc67 = 0ull;
            const float* Ecol = E_s + j;
#pragma unroll 4
            for (int i = 0; i < L_TAG; i++) {
                unsigned long long e2 = pack_dup(Ecol[i * LP]);
                const ulonglong2 P0 = *(const ulonglong2*)(bufR + i * PSTR);
                const ulonglong2 P1 = *(const ulonglong2*)(bufR + i * PSTR + 4);
                fma2(acc01, e2, P0.x);
                fma2(acc23, e2, P0.y);
                fma2(acc45, e2, P1.x);
                fma2(acc67, e2, P1.y);
            }
            float u[B_SEQ];
            unpack2(acc01, u[0], u[1]);
            unpack2(acc23, u[2], u[3]);
            unpack2(acc45, u[4], u[5]);
            unpack2(acc67, u[6], u[7]);

            float rk[B_SEQ] = {rkA.x, rkA.y, rkA.z, rkA.w, rkB.x, rkB.y, rkB.z, rkB.w};
#pragma unroll
            for (int b = 0; b < B_SEQ; b++) {
                float e = __expf(m_j + sc[b]);
                float wn = u[b] * e * rk[b];
                if (t < len[b]) w[b] = wn;
            }
            *(float4*)&bufW[j * PSTR]     = make_float4(w[0], w[1], w[2], w[3]);
            *(float4*)&bufW[j * PSTR + 4] = make_float4(w[4], w[5], w[6], w[7]);

            if (lane == 0) {   // anchor owner: j = 32*wid
                int b0 = 2 * wid, b1 = b0 + 1;
                rkW[b0] = __fdividef(1.0f, w[b0]);
                rkW[b1] = __fdividef(1.0f, w[b1]);
                if (t < len[b0]) { C0 += pend0; pend0 = __logf(w[b0]); }
                if (t < len[b1]) { C1 += pend1; pend1 = __logf(w[b1]); }
            }
        } else {
            // Warp 4: column j=128, lane-parallel over i.
            int l = tid - 128;
            float accw[B_SEQ];
#pragma unroll
            for (int b = 0; b < B_SEQ; b++) accw[b] = 0.0f;
            for (int i = l; i < L_TAG; i += 32) {
                float e = E_s[i * LP + 128];
                float4 pA = *(const float4*)(bufR + i * PSTR);
                float4 pB = *(const float4*)(bufR + i * PSTR + 4);
                accw[0] = fmaf(e, pA.x, accw[0]);
                accw[1] = fmaf(e, pA.y, accw[1]);
                accw[2] = fmaf(e, pA.z, accw[2]);
                accw[3] = fmaf(e, pA.w, accw[3]);
                accw[4] = fmaf(e, pB.x, accw[4]);
                accw[5] = fmaf(e, pB.y, accw[5]);
                accw[6] = fmaf(e, pB.z, accw[6]);
                accw[7] = fmaf(e, pB.w, accw[7]);
            }
#pragma unroll
            for (int o = 16; o; o >>= 1) {
#pragma unroll
                for (int b = 0; b < B_SEQ; b++)
                    accw[b] += __shfl_xor_sync(0xffffffffu, accw[b], o);
            }
            if (l == 0) {
                float4 rkA = *(const float4*)rkR;
                float4 rkB = *(const float4*)(rkR + 4);
                float rk[B_SEQ] = {rkA.x, rkA.y, rkA.z, rkA.w, rkB.x, rkB.y, rkB.z, rkB.w};
#pragma unroll
                for (int b = 0; b < B_SEQ; b++) {
                    float scv = sp[b][t * L_TAG];   // j=128 pointer
                    float e = __expf(m_j + scv);
                    float wn = accw[b] * e * rk[b];
                    if (t < len[b]) w[b] = wn;
                }
                *(float4*)&bufW[128 * PSTR]     = make_float4(w[0], w[1], w[2], w[3]);
                *(float4*)&bufW[128 * PSTR + 4] = make_float4(w[4], w[5], w[6], w[7]);
            }
        }
        __syncthreads();
    }

    // ---- Epilogue: reconstruct alpha = log(w) + C_b, then logsumexp + numerator.
    if (lane == 0 && wid < 4) {
        int b0 = 2 * wid;
        c_s[b0] = C0;
        c_s[b0 + 1] = C1;
    }
    __syncthreads();
    if (own) {
        float e_j = endt[j];
#pragma unroll
        for (int b = 0; b < B_SEQ; b++)
            red0[b * LP + j] = __logf(w[b]) + c_s[b] + e_j;
    }
    __syncthreads();
    if (tid < 128) {
        int g = tid >> 4, l16 = tid & 15;
        float mx = -INFINITY;
        for (int jj = l16; jj < LP; jj += 16) mx = fmaxf(mx, red0[g * LP + jj]);
#pragma unroll
        for (int o = 8; o; o >>= 1) mx = fmaxf(mx, __shfl_xor_sync(0xffffffffu, mx, o));
        if (l16 == 0) amax_s[g] = mx;
    }
    __syncthreads();
    if (tid < 128) {
        int g = tid >> 4, l16 = tid & 15;
        float am = amax_s[g];
        float ssum = 0.0f;
        for (int jj = l16; jj < L_TAG; jj += 16) ssum += __expf(red0[g * LP + jj] - am);
#pragma unroll
        for (int o = 8; o; o >>= 1) ssum += __shfl_xor_sync(0xffffffffu, ssum, o);
        if (l16 == 0) denom_s[g] = __logf(ssum) + am;

        // Numerator: gold-path score.
        int sq = g_order[grp * B_SEQ + g];
        int ln = lengths[sq];
        float nacc = 0.0f;
        for (int t = l16; t < ln; t += 16) {
            int gt = gold[sq * T_LEN + t];
            nacc += score[(size_t)(sq * T_LEN + t) * L_TAG + gt];
            if (t >= 1) {
                int gp = gold[sq * T_LEN + t - 1];
                nacc += trans[gp * L_TAG + gt];
            }
        }
#pragma unroll
        for (int o = 8; o; o >>= 1) nacc += __shfl_xor_sync(0xffffffffu, nacc, o);
        if (l16 == 0) {
            int g0 = gold[sq * T_LEN];
            int gl = gold[sq * T_LEN + ln - 1];
            numer_s[g] = nacc + startt[g0] + endt[gl];
        }
    }
    __syncthreads();
    if (tid == 0) {
        float part = 0.0f;
#pragma unroll
        for (int b = 0; b < B_SEQ; b++) part += numer_s[b] - denom_s[b];
        g_partial[blockIdx.x] = part;
    }
}

// ---------------------------------------------------------------------------
__global__ void final_kernel(float* __restrict__ out) {
    __shared__ float s[NBLK];
    int tid = threadIdx.x;
    s[tid] = g_partial[tid];
    __syncthreads();
    for (int o = NBLK / 2; o; o >>= 1) {
        if (tid < o) s[tid] += s[tid + o];
        __syncthreads();
    }
    if (tid == 0) out[0] = s[0];
}

extern "C" void kernel_launch(void* const* d_in, const int* in_sizes, int n_in,
                              void* d_out, int out_size) {
    (void)in_sizes; (void)n_in; (void)out_size;
    const float* score   = (const float*)d_in[0];
    const float* trans   = (const float*)d_in[1];
    const float* startt  = (const float*)d_in[2];
    const float* endt    = (const float*)d_in[3];
    const int*   gold    = (const int*)d_in[4];
    const int*   lengths = (const int*)d_in[5];
    float*       out     = (float*)d_out;

    size_t smem = (size_t)(L_TAG * LP + 2 * PBUF + 8 * LP + 16 + 8 + 8 + 8 + 8) * sizeof(float);
    cudaFuncSetAttribute(crf_main, cudaFuncAttributeMaxDynamicSharedMemorySize, (int)smem);

    prep_E<<<1, 256>>>(trans);
    sort_kernel<<<N_SEQ / 256, 256>>>(lengths);
    crf_main<<<NBLK, MTHREADS, smem>>>(score, trans, startt, endt, gold, lengths);
    final_kernel<<<1, NBLK>>>(out);
}